// round 8
// baseline (speedup 1.0000x reference)
#include <cuda_runtime.h>
#include <cuda_fp16.h>
#include <cstdint>
#include <cstddef>

// ScaledDotProductAttention B=16, S=2048, D=128 fp32 (sm_100 classic mma.sync).
// Out = context [16,2048,128] ++ attention [16,2048,2048].
//
// Round 8 = round-6 winner (256-thread CTA, LDSM, fp16 GEMMs) + the
// normalization pass FUSED as a per-CTA tail: after its 32 stages, each CTA
// rescales its own contiguous 1MB attention block (coalesced float4, rinv in
// smem). Wave-1 tails overlap wave-2 compute (attn1 ran at only 21% DRAM),
// deleting the separate 79us scale_att kernel.
//
//  cvt_kv : K -> fp16 [b][key][d]; V -> fp16 transposed pair-words.
//  attn1  : CTA=(b,128 q-rows), 8 warps x 16 rows; 64-key stages, 4 buffers,
//           cp.async 3-deep, 1 sync/stage; K/V frags via ldmatrix.x4;
//           S=QK^T, p=exp2(S) -> unnormalized att store, P packed to A-frags
//           in regs, O += P V; context=O/l; then tail: att *= 1/l.

#define BATCH 16
#define SEQ   2048
#define DIM   128

#define KSTR  68                 // words per key row (64+4)
#define VSTR2 36                 // words per d row (32+4)
#define KBUF (64*KSTR)           // 4352 words
#define VBUF (128*VSTR2)         // 4608 words
#define STAGE_W (KBUF + VBUF)    // 8960 words
#define NBUF 4
#define RINV_W (NBUF * STAGE_W)          // 128 words of rinv after buffers
#define SMEM_WORDS (RINV_W + 128)        // 35968 words = 143,872 B

__device__ __half   g_kh[BATCH * SEQ * DIM];
__device__ uint32_t g_vh[BATCH * DIM * (SEQ / 2)];   // [b][d][pair]

__device__ __forceinline__ uint32_t smem_u32(const void* p) {
    uint32_t a;
    asm("{ .reg .u64 t; cvta.to.shared.u64 t, %1; cvt.u32.u64 %0, t; }" : "=r"(a) : "l"(p));
    return a;
}
__device__ __forceinline__ float ex2(float x) {
    float y; asm("ex2.approx.f32 %0, %1;" : "=f"(y) : "f"(x)); return y;
}
__device__ __forceinline__ uint32_t h2(float a, float b) {
    uint32_t r;
    asm("cvt.rn.f16x2.f32 %0, %2, %1;" : "=r"(r) : "f"(a), "f"(b));
    return r;
}
__device__ __forceinline__ void mma_f16(float& c0, float& c1, float& c2, float& c3,
                                        uint32_t a0, uint32_t a1, uint32_t a2, uint32_t a3,
                                        uint32_t b0, uint32_t b1) {
    asm("mma.sync.aligned.m16n8k16.row.col.f32.f16.f16.f32 "
        "{%0,%1,%2,%3}, {%4,%5,%6,%7}, {%8,%9}, {%0,%1,%2,%3};"
        : "+f"(c0), "+f"(c1), "+f"(c2), "+f"(c3)
        : "r"(a0), "r"(a1), "r"(a2), "r"(a3), "r"(b0), "r"(b1));
}
__device__ __forceinline__ void ldsm4(uint32_t& r0, uint32_t& r1, uint32_t& r2,
                                      uint32_t& r3, uint32_t addr) {
    asm volatile("ldmatrix.sync.aligned.m8n8.x4.shared.b16 {%0,%1,%2,%3}, [%4];"
                 : "=r"(r0), "=r"(r1), "=r"(r2), "=r"(r3) : "r"(addr));
}

#define CP16(dst, src) \
    asm volatile("cp.async.cg.shared.global [%0], [%1], 16;" :: "r"(dst), "l"(src))
#define CP_COMMIT() asm volatile("cp.async.commit_group;" ::: "memory")
#define CP_WAIT(n)  asm volatile("cp.async.wait_group %0;" :: "n"(n) : "memory")

// stage s = 64 keys: K 64 rows x 256B; V 128 d-rows x 128B slice. 256 threads.
__device__ __forceinline__ void issue_stage(uint32_t smb, const __half* kh,
                                            const uint32_t* vh, int s, int tid) {
    const uint32_t base = smb + (uint32_t)((s & (NBUF - 1)) * STAGE_W) * 4;
    const char* kp = (const char*)(kh + (size_t)s * 64 * DIM);
    const char* vp = (const char*)(vh + (size_t)s * 32);      // row stride 4KB
#pragma unroll
    for (int j = 0; j < 4; j++) {
        int i = tid + j * 256;
        int kr = i >> 4, kc = i & 15;          // K: 64 rows x 16 chunks
        CP16(base + (uint32_t)(kr * KSTR * 4 + kc * 16), kp + kr * 256 + kc * 16);
        int vr = i >> 3, vc = i & 7;           // V: 128 rows x 8 chunks
        CP16(base + (uint32_t)(KBUF * 4 + vr * VSTR2 * 4 + vc * 16),
             vp + (size_t)vr * (SEQ / 2) * 4 + vc * 16);
    }
    CP_COMMIT();
}

// K -> fp16 elementwise; V -> fp16 transposed pair-words via smem tile.
__global__ void __launch_bounds__(256)
cvt_kv(const float* __restrict__ k, const float* __restrict__ v) {
    const int tid = threadIdx.x;
    const size_t nkw = (size_t)BATCH * SEQ * DIM / 2;
    for (size_t w = (size_t)blockIdx.x * 256 + tid; w < nkw; w += (size_t)gridDim.x * 256) {
        float2 kf = ((const float2*)k)[w];
        ((uint32_t*)g_kh)[w] = h2(kf.x, kf.y);
    }
    __shared__ float s[64][33];
    const int bx = blockIdx.x;            // 2048 blocks
    const int b  = bx >> 7;
    const int pt = (bx >> 2) & 31;
    const int dt = bx & 3;
    const float* vb = v + ((size_t)b * SEQ + pt * 64) * DIM + dt * 32;
#pragma unroll
    for (int j = 0; j < 8; j++) {
        int i = tid + j * 256;
        int kk = i >> 5, dd = i & 31;
        s[kk][dd] = vb[(size_t)kk * DIM + dd];
    }
    __syncthreads();
    uint32_t* dst = g_vh + (size_t)b * DIM * (SEQ / 2) + (size_t)(dt * 32) * (SEQ / 2) + pt * 32;
#pragma unroll
    for (int j = 0; j < 4; j++) {
        int i = tid + j * 256;
        int pp = i & 31, dd = i >> 5;
        dst[(size_t)dd * (SEQ / 2) + pp] = h2(s[2 * pp][dd], s[2 * pp + 1][dd]);
    }
}

__global__ void __launch_bounds__(256, 1)
attn1(const float* __restrict__ qg_, float* __restrict__ out) {
    extern __shared__ float sm[];
    const uint32_t smb = smem_u32(sm);

    const int tid = threadIdx.x;
    const int warp = tid >> 5, lane = tid & 31;
    const int g = lane >> 2, qq = lane & 3;
    const int row0 = warp * 16 + g;

    const int b = blockIdx.y, qb = blockIdx.x;
    const float* qg = qg_ + ((size_t)b * SEQ + (size_t)qb * 128) * DIM;
    const __half* kh = g_kh + (size_t)b * SEQ * DIM;
    const uint32_t* vh = g_vh + (size_t)b * DIM * (SEQ / 2);
    float* ctx = out + ((size_t)b * SEQ + (size_t)qb * 128) * DIM;
    float* att = out + (size_t)BATCH * SEQ * DIM
                     + ((size_t)b * SEQ + (size_t)qb * 128) * SEQ;

    issue_stage(smb, kh, vh, 0, tid);
    issue_stage(smb, kh, vh, 1, tid);
    issue_stage(smb, kh, vh, 2, tid);

    // Q fp16 A-frags (scale*log2e folded)
    const float qsc = 0.088388347648318447f * 1.4426950408889634f;
    const float* q0 = qg + (size_t)row0 * DIM;
    const float* q1 = q0 + 8 * DIM;
    uint32_t qa[8][4];
#pragma unroll
    for (int t = 0; t < 8; t++) {
        int c0 = 16 * t + 2 * qq;
        qa[t][0] = h2(q0[c0] * qsc,     q0[c0 + 1] * qsc);
        qa[t][1] = h2(q1[c0] * qsc,     q1[c0 + 1] * qsc);
        qa[t][2] = h2(q0[c0 + 8] * qsc, q0[c0 + 9] * qsc);
        qa[t][3] = h2(q1[c0 + 8] * qsc, q1[c0 + 9] * qsc);
    }

    float o[16][4];
#pragma unroll
    for (int i = 0; i < 16; i++) { o[i][0] = o[i][1] = o[i][2] = o[i][3] = 0.f; }
    float l0 = 0.f, l1 = 0.f;

    const uint32_t kln = (uint32_t)((lane & 7) * KSTR * 4 + 16 * (lane >> 3));
    const uint32_t vln = (uint32_t)((lane & 7) * VSTR2 * 4 + ((lane >> 3) & 1) * 16
                                    + (lane >> 4) * 8 * VSTR2 * 4);

    for (int s = 0; s < 32; ++s) {
        if (s <= 28) { CP_WAIT(2); } else { CP_WAIT(0); }
        __syncthreads();
        if (s <= 28) issue_stage(smb, kh, vh, s + 3, tid);

        const uint32_t kbase = smb + (uint32_t)((s & (NBUF - 1)) * STAGE_W) * 4 + kln;
        const uint32_t vbase = smb + (uint32_t)((s & (NBUF - 1)) * STAGE_W + KBUF) * 4 + vln;

        // ---- S = Q K^T : 16 q-rows x 64 keys ----
        float cf[8][4];
#pragma unroll
        for (int i = 0; i < 8; i++) { cf[i][0] = cf[i][1] = cf[i][2] = cf[i][3] = 0.f; }
#pragma unroll
        for (int u = 0; u < 4; u++) {
#pragma unroll
            for (int nt = 0; nt < 8; nt++) {
                uint32_t b00, b01, b10, b11;
                ldsm4(b00, b01, b10, b11, kbase + (uint32_t)(nt * 8 * KSTR * 4 + u * 64));
                mma_f16(cf[nt][0], cf[nt][1], cf[nt][2], cf[nt][3],
                        qa[2*u][0], qa[2*u][1], qa[2*u][2], qa[2*u][3], b00, b01);
                mma_f16(cf[nt][0], cf[nt][1], cf[nt][2], cf[nt][3],
                        qa[2*u+1][0], qa[2*u+1][1], qa[2*u+1][2], qa[2*u+1][3], b10, b11);
            }
        }

        // ---- p = exp2, row sums, unnormalized attention store ----
        float* a0p = att + (size_t)row0 * SEQ + 64 * s + 2 * qq;
        float* a1p = a0p + (size_t)8 * SEQ;
#pragma unroll
        for (int nt = 0; nt < 8; nt++) {
            float p0 = ex2(cf[nt][0]);
            float p1 = ex2(cf[nt][1]);
            float p2 = ex2(cf[nt][2]);
            float p3 = ex2(cf[nt][3]);
            l0 += p0 + p1; l1 += p2 + p3;
            *(float2*)(a0p + 8 * nt) = make_float2(p0, p1);
            *(float2*)(a1p + 8 * nt) = make_float2(p2, p3);
            cf[nt][0] = p0; cf[nt][1] = p1; cf[nt][2] = p2; cf[nt][3] = p3;
        }

        // ---- O += P V : P accum layout == A-frag layout ----
#pragma unroll
        for (int tt = 0; tt < 4; tt++) {
            uint32_t A0 = h2(cf[2*tt][0],   cf[2*tt][1]);
            uint32_t A1 = h2(cf[2*tt][2],   cf[2*tt][3]);
            uint32_t A2 = h2(cf[2*tt+1][0], cf[2*tt+1][1]);
            uint32_t A3 = h2(cf[2*tt+1][2], cf[2*tt+1][3]);
#pragma unroll
            for (int ndp = 0; ndp < 8; ndp++) {
                uint32_t v00, v01, v10, v11;
                ldsm4(v00, v01, v10, v11, vbase + (uint32_t)(tt * 32 + ndp * 16 * VSTR2 * 4));
                mma_f16(o[2*ndp][0], o[2*ndp][1], o[2*ndp][2], o[2*ndp][3],
                        A0, A1, A2, A3, v00, v01);
                mma_f16(o[2*ndp+1][0], o[2*ndp+1][1], o[2*ndp+1][2], o[2*ndp+1][3],
                        A0, A1, A2, A3, v10, v11);
            }
        }
    }

    // ---- context epilogue + rinv -> smem ----
    l0 += __shfl_xor_sync(0xffffffffu, l0, 1);
    l0 += __shfl_xor_sync(0xffffffffu, l0, 2);
    l1 += __shfl_xor_sync(0xffffffffu, l1, 1);
    l1 += __shfl_xor_sync(0xffffffffu, l1, 2);
    const float r0 = 1.0f / l0;
    const float r1 = 1.0f / l1;

    float* c0p = ctx + (size_t)row0 * DIM + 2 * qq;
    float* c1p = c0p + (size_t)8 * DIM;
#pragma unroll
    for (int nd = 0; nd < 16; nd++) {
        *(float2*)(c0p + 8 * nd) = make_float2(o[nd][0] * r0, o[nd][1] * r0);
        *(float2*)(c1p + 8 * nd) = make_float2(o[nd][2] * r1, o[nd][3] * r1);
    }
    if (qq == 0) {
        sm[RINV_W + row0]     = r0;
        sm[RINV_W + row0 + 8] = r1;
    }
    __syncthreads();    // rinv visible + this CTA's global att writes visible

    // ---- fused normalization tail: att block (128 x 2048) *= 1/l ----
    // Coalesced float4; overlaps other CTAs' compute (DRAM was 21% idle-bound).
    float4* ab = (float4*)att;
    #pragma unroll 4
    for (int i = tid; i < 128 * 512; i += 256) {
        float r = sm[RINV_W + (i >> 9)];
        float4 a = ab[i];
        a.x *= r; a.y *= r; a.z *= r; a.w *= r;
        ab[i] = a;
    }
}

__global__ void _noop() {}

extern "C" void kernel_launch(void* const* d_in, const int* in_sizes, int n_in,
                              void* d_out, int out_size) {
    const float* q = (const float*)d_in[0];
    const float* k = (const float*)d_in[1];
    const float* v = (const float*)d_in[2];
    float* out = (float*)d_out;

    cudaFuncSetAttribute(attn1, cudaFuncAttributeMaxDynamicSharedMemorySize,
                         SMEM_WORDS * 4);

    cvt_kv<<<2048, 256>>>(k, v);

    // keep the 4th launch = attn1 (ncu profile position)
    _noop<<<1, 32>>>();
    _noop<<<1, 32>>>();

    dim3 grid(SEQ / 128, BATCH);
    attn1<<<grid, 256, SMEM_WORDS * 4>>>(q, out);
}

// round 9
// speedup vs baseline: 1.1699x; 1.1699x over previous
#include <cuda_runtime.h>
#include <cuda_fp16.h>
#include <cstdint>
#include <cstddef>

// ScaledDotProductAttention B=16, S=2048, D=128 fp32 (sm_100 classic mma.sync).
// Out = context [16,2048,128] ++ attention [16,2048,2048].
//
// Round 9: two-pass recompute normalization inside attn1 (round-6 core).
//  Pass 1: K-only stages; S=QK^T, p=exp2(S), row sums -> rinv kept in the
//          registers of the thread that owns those rows in pass 2.
//  Pass 2: recompute S (bit-identical), store NORMALIZED attention once
//          (268MB written once vs 804MB total before); P packed to fp16
//          A-frags with x64 scale (subnormal guard), O += P V, context =
//          O * (1/64). scale_att kernel deleted.
//  cvt_kv : K -> fp16 [b][key][d]; V -> fp16 transposed pair-words.

#define BATCH 16
#define SEQ   2048
#define DIM   128

#define KSTR  68                 // words per key row (64+4)
#define VSTR2 36                 // words per d row (32+4)
#define KBUF (64*KSTR)           // 4352 words
#define VBUF (128*VSTR2)         // 4608 words
#define STAGE_W (KBUF + VBUF)    // 8960 words
#define NBUF 4
#define SMEM_WORDS (NBUF * STAGE_W)   // 35840 words = 143,360 B

__device__ __half   g_kh[BATCH * SEQ * DIM];
__device__ uint32_t g_vh[BATCH * DIM * (SEQ / 2)];   // [b][d][pair]

__device__ __forceinline__ uint32_t smem_u32(const void* p) {
    uint32_t a;
    asm("{ .reg .u64 t; cvta.to.shared.u64 t, %1; cvt.u32.u64 %0, t; }" : "=r"(a) : "l"(p));
    return a;
}
__device__ __forceinline__ float ex2(float x) {
    float y; asm("ex2.approx.f32 %0, %1;" : "=f"(y) : "f"(x)); return y;
}
__device__ __forceinline__ uint32_t h2(float a, float b) {
    uint32_t r;
    asm("cvt.rn.f16x2.f32 %0, %2, %1;" : "=r"(r) : "f"(a), "f"(b));
    return r;
}
__device__ __forceinline__ void mma_f16(float& c0, float& c1, float& c2, float& c3,
                                        uint32_t a0, uint32_t a1, uint32_t a2, uint32_t a3,
                                        uint32_t b0, uint32_t b1) {
    asm("mma.sync.aligned.m16n8k16.row.col.f32.f16.f16.f32 "
        "{%0,%1,%2,%3}, {%4,%5,%6,%7}, {%8,%9}, {%0,%1,%2,%3};"
        : "+f"(c0), "+f"(c1), "+f"(c2), "+f"(c3)
        : "r"(a0), "r"(a1), "r"(a2), "r"(a3), "r"(b0), "r"(b1));
}
__device__ __forceinline__ void ldsm4(uint32_t& r0, uint32_t& r1, uint32_t& r2,
                                      uint32_t& r3, uint32_t addr) {
    asm volatile("ldmatrix.sync.aligned.m8n8.x4.shared.b16 {%0,%1,%2,%3}, [%4];"
                 : "=r"(r0), "=r"(r1), "=r"(r2), "=r"(r3) : "r"(addr));
}

#define CP16(dst, src) \
    asm volatile("cp.async.cg.shared.global [%0], [%1], 16;" :: "r"(dst), "l"(src))
#define CP_COMMIT() asm volatile("cp.async.commit_group;" ::: "memory")
#define CP_WAIT(n)  asm volatile("cp.async.wait_group %0;" :: "n"(n) : "memory")

// full stage: K 64 rows x 256B + V 128 d-rows x 128B slice. 256 threads.
__device__ __forceinline__ void issue_stage(uint32_t smb, const __half* kh,
                                            const uint32_t* vh, int s, int tid) {
    const uint32_t base = smb + (uint32_t)((s & (NBUF - 1)) * STAGE_W) * 4;
    const char* kp = (const char*)(kh + (size_t)s * 64 * DIM);
    const char* vp = (const char*)(vh + (size_t)s * 32);
#pragma unroll
    for (int j = 0; j < 4; j++) {
        int i = tid + j * 256;
        int kr = i >> 4, kc = i & 15;
        CP16(base + (uint32_t)(kr * KSTR * 4 + kc * 16), kp + kr * 256 + kc * 16);
        int vr = i >> 3, vc = i & 7;
        CP16(base + (uint32_t)(KBUF * 4 + vr * VSTR2 * 4 + vc * 16),
             vp + (size_t)vr * (SEQ / 2) * 4 + vc * 16);
    }
    CP_COMMIT();
}

// K-only stage for pass 1
__device__ __forceinline__ void issue_k_stage(uint32_t smb, const __half* kh,
                                              int s, int tid) {
    const uint32_t base = smb + (uint32_t)((s & (NBUF - 1)) * STAGE_W) * 4;
    const char* kp = (const char*)(kh + (size_t)s * 64 * DIM);
#pragma unroll
    for (int j = 0; j < 4; j++) {
        int i = tid + j * 256;
        int kr = i >> 4, kc = i & 15;
        CP16(base + (uint32_t)(kr * KSTR * 4 + kc * 16), kp + kr * 256 + kc * 16);
    }
    CP_COMMIT();
}

// K -> fp16 elementwise; V -> fp16 transposed pair-words via smem tile.
__global__ void __launch_bounds__(256)
cvt_kv(const float* __restrict__ k, const float* __restrict__ v) {
    const int tid = threadIdx.x;
    const size_t nkw = (size_t)BATCH * SEQ * DIM / 2;
    for (size_t w = (size_t)blockIdx.x * 256 + tid; w < nkw; w += (size_t)gridDim.x * 256) {
        float2 kf = ((const float2*)k)[w];
        ((uint32_t*)g_kh)[w] = h2(kf.x, kf.y);
    }
    __shared__ float s[64][33];
    const int bx = blockIdx.x;            // 2048 blocks
    const int b  = bx >> 7;
    const int pt = (bx >> 2) & 31;
    const int dt = bx & 3;
    const float* vb = v + ((size_t)b * SEQ + pt * 64) * DIM + dt * 32;
#pragma unroll
    for (int j = 0; j < 8; j++) {
        int i = tid + j * 256;
        int kk = i >> 5, dd = i & 31;
        s[kk][dd] = vb[(size_t)kk * DIM + dd];
    }
    __syncthreads();
    uint32_t* dst = g_vh + (size_t)b * DIM * (SEQ / 2) + (size_t)(dt * 32) * (SEQ / 2) + pt * 32;
#pragma unroll
    for (int j = 0; j < 4; j++) {
        int i = tid + j * 256;
        int pp = i & 31, dd = i >> 5;
        dst[(size_t)dd * (SEQ / 2) + pp] = h2(s[2 * pp][dd], s[2 * pp + 1][dd]);
    }
}

__global__ void __launch_bounds__(256, 1)
attn1(const float* __restrict__ qg_, float* __restrict__ out) {
    extern __shared__ float sm[];
    const uint32_t smb = smem_u32(sm);

    const int tid = threadIdx.x;
    const int warp = tid >> 5, lane = tid & 31;
    const int g = lane >> 2, qq = lane & 3;
    const int row0 = warp * 16 + g;

    const int b = blockIdx.y, qb = blockIdx.x;
    const float* qg = qg_ + ((size_t)b * SEQ + (size_t)qb * 128) * DIM;
    const __half* kh = g_kh + (size_t)b * SEQ * DIM;
    const uint32_t* vh = g_vh + (size_t)b * DIM * (SEQ / 2);
    float* ctx = out + ((size_t)b * SEQ + (size_t)qb * 128) * DIM;
    float* att = out + (size_t)BATCH * SEQ * DIM
                     + ((size_t)b * SEQ + (size_t)qb * 128) * SEQ;

    issue_k_stage(smb, kh, 0, tid);
    issue_k_stage(smb, kh, 1, tid);
    issue_k_stage(smb, kh, 2, tid);

    // Q fp16 A-frags (scale*log2e folded)
    const float qsc = 0.088388347648318447f * 1.4426950408889634f;
    const float* q0 = qg + (size_t)row0 * DIM;
    const float* q1 = q0 + 8 * DIM;
    uint32_t qa[8][4];
#pragma unroll
    for (int t = 0; t < 8; t++) {
        int c0 = 16 * t + 2 * qq;
        qa[t][0] = h2(q0[c0] * qsc,     q0[c0 + 1] * qsc);
        qa[t][1] = h2(q1[c0] * qsc,     q1[c0 + 1] * qsc);
        qa[t][2] = h2(q0[c0 + 8] * qsc, q0[c0 + 9] * qsc);
        qa[t][3] = h2(q1[c0 + 8] * qsc, q1[c0 + 9] * qsc);
    }

    const uint32_t kln = (uint32_t)((lane & 7) * KSTR * 4 + 16 * (lane >> 3));
    const uint32_t vln = (uint32_t)((lane & 7) * VSTR2 * 4 + ((lane >> 3) & 1) * 16
                                    + (lane >> 4) * 8 * VSTR2 * 4);

    // ================= PASS 1: row sums only (K-only stages) =================
    float l0 = 0.f, l1 = 0.f;
    for (int s = 0; s < 32; ++s) {
        if (s <= 28) { CP_WAIT(2); } else { CP_WAIT(0); }
        __syncthreads();
        if (s <= 28) issue_k_stage(smb, kh, s + 3, tid);

        const uint32_t kbase = smb + (uint32_t)((s & (NBUF - 1)) * STAGE_W) * 4 + kln;

        float cf[8][4];
#pragma unroll
        for (int i = 0; i < 8; i++) { cf[i][0] = cf[i][1] = cf[i][2] = cf[i][3] = 0.f; }
#pragma unroll
        for (int u = 0; u < 4; u++) {
#pragma unroll
            for (int nt = 0; nt < 8; nt++) {
                uint32_t b00, b01, b10, b11;
                ldsm4(b00, b01, b10, b11, kbase + (uint32_t)(nt * 8 * KSTR * 4 + u * 64));
                mma_f16(cf[nt][0], cf[nt][1], cf[nt][2], cf[nt][3],
                        qa[2*u][0], qa[2*u][1], qa[2*u][2], qa[2*u][3], b00, b01);
                mma_f16(cf[nt][0], cf[nt][1], cf[nt][2], cf[nt][3],
                        qa[2*u+1][0], qa[2*u+1][1], qa[2*u+1][2], qa[2*u+1][3], b10, b11);
            }
        }
#pragma unroll
        for (int nt = 0; nt < 8; nt++) {
            l0 += ex2(cf[nt][0]) + ex2(cf[nt][1]);
            l1 += ex2(cf[nt][2]) + ex2(cf[nt][3]);
        }
    }

    l0 += __shfl_xor_sync(0xffffffffu, l0, 1);
    l0 += __shfl_xor_sync(0xffffffffu, l0, 2);
    l1 += __shfl_xor_sync(0xffffffffu, l1, 1);
    l1 += __shfl_xor_sync(0xffffffffu, l1, 2);
    const float r0 = 1.0f / l0;
    const float r1 = 1.0f / l1;
    const float r0s = r0 * 64.0f;   // fp16 subnormal guard for P packing
    const float r1s = r1 * 64.0f;

    // ================= PASS 2: normalized store + PV =================
    __syncthreads();                 // pass-1 buffer reads done everywhere
    issue_stage(smb, kh, vh, 0, tid);
    issue_stage(smb, kh, vh, 1, tid);
    issue_stage(smb, kh, vh, 2, tid);

    float o[16][4];
#pragma unroll
    for (int i = 0; i < 16; i++) { o[i][0] = o[i][1] = o[i][2] = o[i][3] = 0.f; }

    for (int s = 0; s < 32; ++s) {
        if (s <= 28) { CP_WAIT(2); } else { CP_WAIT(0); }
        __syncthreads();
        if (s <= 28) issue_stage(smb, kh, vh, s + 3, tid);

        const uint32_t kbase = smb + (uint32_t)((s & (NBUF - 1)) * STAGE_W) * 4 + kln;
        const uint32_t vbase = smb + (uint32_t)((s & (NBUF - 1)) * STAGE_W + KBUF) * 4 + vln;

        // ---- S = Q K^T (bit-identical to pass 1) ----
        float cf[8][4];
#pragma unroll
        for (int i = 0; i < 8; i++) { cf[i][0] = cf[i][1] = cf[i][2] = cf[i][3] = 0.f; }
#pragma unroll
        for (int u = 0; u < 4; u++) {
#pragma unroll
            for (int nt = 0; nt < 8; nt++) {
                uint32_t b00, b01, b10, b11;
                ldsm4(b00, b01, b10, b11, kbase + (uint32_t)(nt * 8 * KSTR * 4 + u * 64));
                mma_f16(cf[nt][0], cf[nt][1], cf[nt][2], cf[nt][3],
                        qa[2*u][0], qa[2*u][1], qa[2*u][2], qa[2*u][3], b00, b01);
                mma_f16(cf[nt][0], cf[nt][1], cf[nt][2], cf[nt][3],
                        qa[2*u+1][0], qa[2*u+1][1], qa[2*u+1][2], qa[2*u+1][3], b10, b11);
            }
        }

        // ---- p_norm = exp2(S) * rinv -> FINAL attention store ----
        float* a0p = att + (size_t)row0 * SEQ + 64 * s + 2 * qq;
        float* a1p = a0p + (size_t)8 * SEQ;
#pragma unroll
        for (int nt = 0; nt < 8; nt++) {
            float p0 = ex2(cf[nt][0]) * r0;
            float p1 = ex2(cf[nt][1]) * r0;
            float p2 = ex2(cf[nt][2]) * r1;
            float p3 = ex2(cf[nt][3]) * r1;
            *(float2*)(a0p + 8 * nt) = make_float2(p0, p1);
            *(float2*)(a1p + 8 * nt) = make_float2(p2, p3);
            cf[nt][0] = p0 * 64.0f; cf[nt][1] = p1 * 64.0f;   // x64 for fp16 range
            cf[nt][2] = p2 * 64.0f; cf[nt][3] = p3 * 64.0f;
        }

        // ---- O += (64*P_norm) V ----
#pragma unroll
        for (int tt = 0; tt < 4; tt++) {
            uint32_t A0 = h2(cf[2*tt][0],   cf[2*tt][1]);
            uint32_t A1 = h2(cf[2*tt][2],   cf[2*tt][3]);
            uint32_t A2 = h2(cf[2*tt+1][0], cf[2*tt+1][1]);
            uint32_t A3 = h2(cf[2*tt+1][2], cf[2*tt+1][3]);
#pragma unroll
            for (int ndp = 0; ndp < 8; ndp++) {
                uint32_t v00, v01, v10, v11;
                ldsm4(v00, v01, v10, v11, vbase + (uint32_t)(tt * 32 + ndp * 16 * VSTR2 * 4));
                mma_f16(o[2*ndp][0], o[2*ndp][1], o[2*ndp][2], o[2*ndp][3],
                        A0, A1, A2, A3, v00, v01);
                mma_f16(o[2*ndp+1][0], o[2*ndp+1][1], o[2*ndp+1][2], o[2*ndp+1][3],
                        A0, A1, A2, A3, v10, v11);
            }
        }
    }

    // ---- context = O / 64 ----
    const float inv64 = 0.015625f;
    float* c0p = ctx + (size_t)row0 * DIM + 2 * qq;
    float* c1p = c0p + (size_t)8 * DIM;
#pragma unroll
    for (int nd = 0; nd < 16; nd++) {
        *(float2*)(c0p + 8 * nd) = make_float2(o[nd][0] * inv64, o[nd][1] * inv64);
        *(float2*)(c1p + 8 * nd) = make_float2(o[nd][2] * inv64, o[nd][3] * inv64);
    }
}

__global__ void _noop() {}

extern "C" void kernel_launch(void* const* d_in, const int* in_sizes, int n_in,
                              void* d_out, int out_size) {
    const float* q = (const float*)d_in[0];
    const float* k = (const float*)d_in[1];
    const float* v = (const float*)d_in[2];
    float* out = (float*)d_out;

    cudaFuncSetAttribute(attn1, cudaFuncAttributeMaxDynamicSharedMemorySize,
                         SMEM_WORDS * 4);

    cvt_kv<<<2048, 256>>>(k, v);

    // keep the 4th launch = attn1 (ncu profile position)
    _noop<<<1, 32>>>();
    _noop<<<1, 32>>>();

    dim3 grid(SEQ / 128, BATCH);
    attn1<<<grid, 256, SMEM_WORDS * 4>>>(q, out);
}